// round 3
// baseline (speedup 1.0000x reference)
#include <cuda_runtime.h>
#include <cuda_bf16.h>
#include <cstdint>

typedef unsigned long long ull;

#define VV 32000
#define EE 32
#define HH 128
#define BB 2
#define TT 512
#define RR (BB*TT)                       // 1024
#define OFF_HID (RR*VV)                  // 32768000
#define OFF_W   (OFF_HID + BB*HH)        // 32768256

// ---------------- scratch (static device globals; no allocation) ----------------
__device__ float g_xp [RR*HH];
__device__ float g_rnn[RR*HH];
__device__ float g_q  [RR*HH];
__device__ float g_k  [RR*HH];
__device__ float g_ctx[RR*HH];
__device__ float g_prj[RR*HH];
__device__ int   g_x64;

// ---------------- helpers ----------------
__device__ __forceinline__ void fma2(ull &d, ull a, ull b) {
    asm("fma.rn.f32x2 %0, %1, %2, %0;" : "+l"(d) : "l"(a), "l"(b));
}
__device__ __forceinline__ ull pack2(float a, float b) {
    ull r;
    asm("mov.b64 %0, {%1, %2};" : "=l"(r) : "r"(__float_as_uint(a)), "r"(__float_as_uint(b)));
    return r;
}
__device__ __forceinline__ float ull_lo(ull u){ return __uint_as_float((unsigned)(u & 0xffffffffull)); }
__device__ __forceinline__ float ull_hi(ull u){ return __uint_as_float((unsigned)(u >> 32)); }

// accurate tanh: 2 MUFU, rel err ~1e-6 (used where accuracy matters: RNN recurrence)
__device__ __forceinline__ float tanh_fast(float x) {
    float e = __expf(2.0f * x);
    return 1.0f - __fdividef(2.0f, e + 1.0f);
}
// HW tanh: 1 MUFU, abs err ~5e-4 (attention scores only)
__device__ __forceinline__ float tanh_approx(float x) {
    float y;
    asm("tanh.approx.f32 %0, %1;" : "=f"(y) : "f"(x));
    return y;
}

// ---------------- K0: detect int64 vs int32 ids ----------------
__global__ void detect_kernel(const int* __restrict__ x32) {
    __shared__ int bad;
    if (threadIdx.x == 0) bad = 0;
    __syncthreads();
    for (int i = threadIdx.x; i < 512; i += blockDim.x)
        if (x32[2*i + 1] != 0) atomicExch(&bad, 1);
    __syncthreads();
    if (threadIdx.x == 0) g_x64 = bad ? 0 : 1;
}

// ---------------- K1: embedding + input projection ----------------
__global__ void embed_kernel(const int* __restrict__ x32,
                             const float* __restrict__ et,
                             const float* __restrict__ W_ih,
                             const float* __restrict__ b_ih,
                             const float* __restrict__ b_hh) {
    __shared__ float e_sh[EE];
    __shared__ float Wsh[HH * 33];
    int r = blockIdx.x;
    int h = threadIdx.x;
    for (int j = h; j < HH * EE; j += HH) {
        int hh = j >> 5, ee = j & 31;
        Wsh[hh * 33 + ee] = W_ih[j];
    }
    int id = g_x64 ? x32[2 * r] : x32[r];
    if (h < EE) e_sh[h] = et[id * EE + h];
    __syncthreads();
    float acc = b_ih[h] + b_hh[h];
#pragma unroll
    for (int e = 0; e < EE; e++) acc += Wsh[h * 33 + e] * e_sh[e];
    g_xp[r * HH + h] = acc;
}

// ---------------- K2: sequential RNN scan ----------------
__global__ void rnn_kernel(const float* __restrict__ hidden,
                           const float* __restrict__ W_hh,
                           float* __restrict__ out_hid) {
    __shared__ __align__(16) float h_sh[2][HH];
    int b = blockIdx.x;
    int tid = threadIdx.x;
    int h = tid >> 2, part = tid & 3;

    ull w2[16];
    {
        const ulonglong2* wp = (const ulonglong2*)(W_hh + h * HH + part * 32);
#pragma unroll
        for (int i = 0; i < 8; i++) { ulonglong2 v = wp[i]; w2[2*i] = v.x; w2[2*i+1] = v.y; }
    }
    if (tid < HH) h_sh[0][tid] = hidden[b * HH + tid];
    __syncthreads();

    const float* xpb = g_xp + b * TT * HH;
    float* rnnb = g_rnn + b * TT * HH;

    float xnext = xpb[h];   // prefetch t=0
    for (int t = 0; t < TT; t++) {
        float xcur = xnext;
        if (t + 1 < TT) xnext = xpb[(t + 1) * HH + h];  // prefetch next, hidden behind dot
        int cur = t & 1;
        const ulonglong2* hp = (const ulonglong2*)(&h_sh[cur][part * 32]);
        ull a0 = 0ull, a1 = 0ull;
#pragma unroll
        for (int i = 0; i < 8; i++) {
            ulonglong2 hh2 = hp[i];
            fma2(a0, w2[2*i],   hh2.x);
            fma2(a1, w2[2*i+1], hh2.y);
        }
        float s = ull_lo(a0) + ull_hi(a0) + ull_lo(a1) + ull_hi(a1);
        s += __shfl_xor_sync(0xffffffffu, s, 1);
        s += __shfl_xor_sync(0xffffffffu, s, 2);
        if (part == 0) {
            float hn = tanh_fast(xcur + s);
            h_sh[cur ^ 1][h] = hn;
            rnnb[t * HH + h] = hn;
        }
        __syncthreads();
    }
    if (part == 0) out_hid[b * HH + h] = h_sh[0][h];
}

// ---------------- K3: q = rnn@W1^T, k = rnn@W2^T  (W in smem once, transposed) ----------------
__global__ __launch_bounds__(256, 2) void qk_kernel(const float* __restrict__ W1,
                                                    const float* __restrict__ W2) {
    extern __shared__ float qsm[];
    float* Wt  = qsm;              // [k=128][h=128] pitch 132
    float* rsh = qsm + 128 * 132;  // [r=32][k=128] pitch 132
    int wsel = blockIdx.x >> 5, tc = blockIdx.x & 31;
    const float* W = wsel ? W2 : W1;
    int tid = threadIdx.x;

#pragma unroll
    for (int it = 0; it < 16; it++) {
        int j = it * 256 + tid;             // 0..4095
        int h = j >> 5, k4 = j & 31;
        float4 f = *(const float4*)&W[h * HH + k4 * 4];
        Wt[(k4 * 4 + 0) * 132 + h] = f.x;
        Wt[(k4 * 4 + 1) * 132 + h] = f.y;
        Wt[(k4 * 4 + 2) * 132 + h] = f.z;
        Wt[(k4 * 4 + 3) * 132 + h] = f.w;
    }
#pragma unroll
    for (int it = 0; it < 4; it++) {
        int j = it * 256 + tid;             // 0..1023
        int r = j >> 5, k4 = j & 31;
        *(float4*)&rsh[r * 132 + k4 * 4] = *(const float4*)&g_rnn[(tc * 32 + r) * HH + k4 * 4];
    }
    __syncthreads();

    int h = tid & 127, rg = tid >> 7;
    float acc[16];
#pragma unroll
    for (int i = 0; i < 16; i++) acc[i] = 0.f;

    for (int k = 0; k < 128; k += 4) {
        float w0 = Wt[(k + 0) * 132 + h];
        float w1 = Wt[(k + 1) * 132 + h];
        float w2v = Wt[(k + 2) * 132 + h];
        float w3 = Wt[(k + 3) * 132 + h];
#pragma unroll
        for (int rr = 0; rr < 16; rr++) {
            float4 rv = *(const float4*)&rsh[(rg * 16 + rr) * 132 + k];
            acc[rr] += w0 * rv.x + w1 * rv.y + w2v * rv.z + w3 * rv.w;
        }
    }
    float* dst = wsel ? g_k : g_q;
#pragma unroll
    for (int rr = 0; rr < 16; rr++)
        dst[(tc * 32 + rg * 16 + rr) * HH + h] = acc[rr];
}

// ---------------- K4: additive attention ----------------
__global__ void attn_kernel(const float* __restrict__ v, float* __restrict__ wout) {
    __shared__ float q_sh[HH], v_sh[HH];
    __shared__ float ksh[64 * 132];
    __shared__ float sc[TT];
    __shared__ float red[8];
    __shared__ float redval;
    __shared__ float ctxp[HH];

    int bx = blockIdx.x;
    int b = bx >> 9, t = bx & 511;
    int tid = threadIdx.x;
    int r = b * TT + t;
    int n = t + 1;

    if (tid < HH) { q_sh[tid] = g_q[r * HH + tid]; v_sh[tid] = v[tid]; }
    __syncthreads();

    int sl = tid >> 2, qq = tid & 3;
    for (int s0 = 0; s0 < n; s0 += 64) {
        int cnt = min(64, n - s0);
        __syncthreads();
        for (int j = tid; j < cnt * HH; j += 256) {
            int ss = j >> 7, hh = j & 127;
            ksh[ss * 132 + hh] = g_k[(b * TT + s0 + ss) * HH + hh];
        }
        __syncthreads();
        float acc = 0.f;
        if (sl < cnt) {
            const float* kr = &ksh[sl * 132];
#pragma unroll 8
            for (int i = 0; i < 32; i++) {
                int hh = qq + 4 * i;
                acc += v_sh[hh] * tanh_approx(q_sh[hh] + kr[hh]);
            }
        }
        acc += __shfl_xor_sync(0xffffffffu, acc, 1);
        acc += __shfl_xor_sync(0xffffffffu, acc, 2);
        if (qq == 0 && sl < cnt) sc[s0 + sl] = acc;
    }
    __syncthreads();

    // softmax over sc[0..n)
    float m = -1e30f;
    for (int s = tid; s < n; s += 256) m = fmaxf(m, sc[s]);
#pragma unroll
    for (int o = 16; o; o >>= 1) m = fmaxf(m, __shfl_xor_sync(0xffffffffu, m, o));
    if ((tid & 31) == 0) red[tid >> 5] = m;
    __syncthreads();
    if (tid == 0) {
        float mm = red[0];
#pragma unroll
        for (int i = 1; i < 8; i++) mm = fmaxf(mm, red[i]);
        redval = mm;
    }
    __syncthreads();
    m = redval;

    float ssum = 0.f;
    for (int s = tid; s < n; s += 256) {
        float e = __expf(sc[s] - m);
        sc[s] = e;
        ssum += e;
    }
#pragma unroll
    for (int o = 16; o; o >>= 1) ssum += __shfl_xor_sync(0xffffffffu, ssum, o);
    __syncthreads();
    if ((tid & 31) == 0) red[tid >> 5] = ssum;
    __syncthreads();
    if (tid == 0) {
        float s2 = 0.f;
#pragma unroll
        for (int i = 0; i < 8; i++) s2 += red[i];
        redval = s2;
    }
    __syncthreads();
    float inv = __fdividef(1.0f, redval);

    for (int s = tid; s < TT; s += 256) {
        float w = (s < n) ? sc[s] * inv : 0.f;
        if (s < n) sc[s] = w;
        wout[(size_t)r * TT + s] = w;
    }
    __syncthreads();

    int h = tid & 127, g = tid >> 7;
    float acc = 0.f;
    for (int s = g; s < n; s += 2)
        acc += sc[s] * g_rnn[(b * TT + s) * HH + h];
    if (g == 1) ctxp[h] = acc;
    __syncthreads();
    if (g == 0) g_ctx[r * HH + h] = acc + ctxp[h];
}

// ---------------- K5: out = relu([rnn|ctx] @ Wp^T + bp) ----------------
__global__ void proj_kernel(const float* __restrict__ Wp, const float* __restrict__ bp) {
    __shared__ float comb[16 * 256];
    __shared__ float Wsh[HH * 33];
    int bx = blockIdx.x;
    int b = bx >> 5, tc = bx & 31;
    int tid = threadIdx.x;
    int h = tid & 127, g = tid >> 7;
    int rbase = b * TT + tc * 16;

    for (int j = tid; j < 16 * HH; j += 256) {
        int tt = j >> 7, k = j & 127;
        comb[tt * 256 + k]        = g_rnn[(rbase + tt) * HH + k];
        comb[tt * 256 + 128 + k]  = g_ctx[(rbase + tt) * HH + k];
    }
    float acc[8];
#pragma unroll
    for (int i = 0; i < 8; i++) acc[i] = 0.f;

    for (int kc = 0; kc < 256; kc += 32) {
        __syncthreads();
        for (int j = tid; j < HH * 32; j += 256) {
            int hh = j >> 5, kk = j & 31;
            Wsh[hh * 33 + kk] = Wp[hh * 256 + kc + kk];
        }
        __syncthreads();
#pragma unroll
        for (int kk = 0; kk < 32; kk++) {
            float w = Wsh[h * 33 + kk];
#pragma unroll
            for (int tt = 0; tt < 8; tt++)
                acc[tt] += w * comb[(g * 8 + tt) * 256 + kc + kk];
        }
    }
    float bb = bp[h];
#pragma unroll
    for (int tt = 0; tt < 8; tt++) {
        float o = fmaxf(acc[tt] + bb, 0.f);
        g_prj[(rbase + g * 8 + tt) * HH + h] = o;
    }
}

// ---------------- K6: logits = prj @ Wfc^T + bfc ----------------
// 128v x 128r tile, K chunked by 32, double-buffered smem, 8v x 8r micro-tile (f32x2 pairs on rows).
__global__ __launch_bounds__(256, 2) void logits_kernel(const float* __restrict__ Wfc,
                                                        const float* __restrict__ bfc,
                                                        float* __restrict__ out) {
    extern __shared__ float sm[];
    float* Asb[2] = { sm,        sm + 4224 };           // [k=32][r=128] pitch 132
    float* Wsb[2] = { sm + 8448, sm + 8448 + 4224 };    // [k=32][v=128] pitch 132
    int vbase = blockIdx.x * 128;
    int rbase = blockIdx.y * 128;
    int tid = threadIdx.x;
    int jr = tid >> 3, jk4 = tid & 7;   // per-it loader coords

    float4 sa[4], sw[4];
    // stage chunk kc into registers
    auto LD = [&](int kc) {
#pragma unroll
        for (int it = 0; it < 4; it++) {
            int rr = it * 32 + jr;
            sa[it] = *(const float4*)&g_prj[(size_t)(rbase + rr) * HH + kc + jk4 * 4];
            sw[it] = *(const float4*)&Wfc [(size_t)(vbase + rr) * HH + kc + jk4 * 4];
        }
    };
    auto ST = [&](int buf) {
        int kk = jk4 * 4;
#pragma unroll
        for (int it = 0; it < 4; it++) {
            int rr = it * 32 + jr;
            Asb[buf][(kk + 0) * 132 + rr] = sa[it].x;
            Asb[buf][(kk + 1) * 132 + rr] = sa[it].y;
            Asb[buf][(kk + 2) * 132 + rr] = sa[it].z;
            Asb[buf][(kk + 3) * 132 + rr] = sa[it].w;
            Wsb[buf][(kk + 0) * 132 + rr] = sw[it].x;
            Wsb[buf][(kk + 1) * 132 + rr] = sw[it].y;
            Wsb[buf][(kk + 2) * 132 + rr] = sw[it].z;
            Wsb[buf][(kk + 3) * 132 + rr] = sw[it].w;
        }
    };

    int tv = tid & 15, tr = tid >> 4;
    int r0 = tr * 8, v0 = tv * 8;

    ull acc[8][4];   // [v][row-pair]
#pragma unroll
    for (int i = 0; i < 8; i++)
#pragma unroll
        for (int p = 0; p < 4; p++) acc[i][p] = 0ull;

    LD(0); ST(0); __syncthreads();

    for (int c = 0; c < 4; c++) {
        int buf = c & 1;
        if (c < 3) LD((c + 1) * 32);         // LDG for next chunk, hidden under compute
        const float* Ab = Asb[buf];
        const float* Wb = Wsb[buf];
#pragma unroll 8
        for (int k = 0; k < 32; k++) {
            ulonglong2 a01 = *(const ulonglong2*)&Ab[k * 132 + r0];
            ulonglong2 a23 = *(const ulonglong2*)&Ab[k * 132 + r0 + 4];
            float4 w0 = *(const float4*)&Wb[k * 132 + v0];
            float4 w1 = *(const float4*)&Wb[k * 132 + v0 + 4];
            ull wd;
            wd = pack2(w0.x, w0.x); fma2(acc[0][0], wd, a01.x); fma2(acc[0][1], wd, a01.y); fma2(acc[0][2], wd, a23.x); fma2(acc[0][3], wd, a23.y);
            wd = pack2(w0.y, w0.y); fma2(acc[1][0], wd, a01.x); fma2(acc[1][1], wd, a01.y); fma2(acc[1][2], wd, a23.x); fma2(acc[1][3], wd, a23.y);
            wd = pack2(w0.z, w0.z); fma2(acc[2][0], wd, a01.x); fma2(acc[2][1], wd, a01.y); fma2(acc[2][2], wd, a23.x); fma2(acc[2][3], wd, a23.y);
            wd = pack2(w0.w, w0.w); fma2(acc[3][0], wd, a01.x); fma2(acc[3][1], wd, a01.y); fma2(acc[3][2], wd, a23.x); fma2(acc[3][3], wd, a23.y);
            wd = pack2(w1.x, w1.x); fma2(acc[4][0], wd, a01.x); fma2(acc[4][1], wd, a01.y); fma2(acc[4][2], wd, a23.x); fma2(acc[4][3], wd, a23.y);
            wd = pack2(w1.y, w1.y); fma2(acc[5][0], wd, a01.x); fma2(acc[5][1], wd, a01.y); fma2(acc[5][2], wd, a23.x); fma2(acc[5][3], wd, a23.y);
            wd = pack2(w1.z, w1.z); fma2(acc[6][0], wd, a01.x); fma2(acc[6][1], wd, a01.y); fma2(acc[6][2], wd, a23.x); fma2(acc[6][3], wd, a23.y);
            wd = pack2(w1.w, w1.w); fma2(acc[7][0], wd, a01.x); fma2(acc[7][1], wd, a01.y); fma2(acc[7][2], wd, a23.x); fma2(acc[7][3], wd, a23.y);
        }
        if (c < 3) ST((c + 1) & 1);
        __syncthreads();
    }

    float4 b0 = *(const float4*)&bfc[vbase + v0];
    float4 b1 = *(const float4*)&bfc[vbase + v0 + 4];
    float bias[8] = { b0.x, b0.y, b0.z, b0.w, b1.x, b1.y, b1.z, b1.w };

#pragma unroll
    for (int p = 0; p < 4; p++) {
#pragma unroll
        for (int half = 0; half < 2; half++) {
            int row = rbase + r0 + 2 * p + half;
            float4 o0, o1;
            o0.x = (half ? ull_hi(acc[0][p]) : ull_lo(acc[0][p])) + bias[0];
            o0.y = (half ? ull_hi(acc[1][p]) : ull_lo(acc[1][p])) + bias[1];
            o0.z = (half ? ull_hi(acc[2][p]) : ull_lo(acc[2][p])) + bias[2];
            o0.w = (half ? ull_hi(acc[3][p]) : ull_lo(acc[3][p])) + bias[3];
            o1.x = (half ? ull_hi(acc[4][p]) : ull_lo(acc[4][p])) + bias[4];
            o1.y = (half ? ull_hi(acc[5][p]) : ull_lo(acc[5][p])) + bias[5];
            o1.z = (half ? ull_hi(acc[6][p]) : ull_lo(acc[6][p])) + bias[6];
            o1.w = (half ? ull_hi(acc[7][p]) : ull_lo(acc[7][p])) + bias[7];
            *(float4*)&out[(size_t)row * VV + vbase + v0]     = o0;
            *(float4*)&out[(size_t)row * VV + vbase + v0 + 4] = o1;
        }
    }
}

// ---------------- launch ----------------
extern "C" void kernel_launch(void* const* d_in, const int* in_sizes, int n_in,
                              void* d_out, int out_size) {
    const int*   x32    = (const int*)  d_in[0];
    const float* hidden = (const float*)d_in[1];
    const float* et     = (const float*)d_in[2];
    const float* W_ih   = (const float*)d_in[3];
    const float* W_hh   = (const float*)d_in[4];
    const float* b_ih   = (const float*)d_in[5];
    const float* b_hh   = (const float*)d_in[6];
    const float* W1     = (const float*)d_in[7];
    const float* W2     = (const float*)d_in[8];
    const float* v      = (const float*)d_in[9];
    const float* Wp     = (const float*)d_in[10];
    const float* bp     = (const float*)d_in[11];
    const float* Wfc    = (const float*)d_in[12];
    const float* bfc    = (const float*)d_in[13];
    float* out = (float*)d_out;

    cudaFuncSetAttribute(qk_kernel,     cudaFuncAttributeMaxDynamicSharedMemorySize, 84480);
    cudaFuncSetAttribute(logits_kernel, cudaFuncAttributeMaxDynamicSharedMemorySize, 67584);

    detect_kernel<<<1, 256>>>(x32);
    embed_kernel<<<RR, HH>>>(x32, et, W_ih, b_ih, b_hh);
    rnn_kernel<<<BB, 512>>>(hidden, W_hh, out + OFF_HID);
    qk_kernel<<<64, 256, 84480>>>(W1, W2);
    attn_kernel<<<RR, 256>>>(v, out + OFF_W);
    proj_kernel<<<64, 256>>>(Wp, bp);
    logits_kernel<<<dim3(VV / 128, RR / 128), 256, 67584>>>(Wfc, bfc, out);
}

// round 5
// speedup vs baseline: 1.9301x; 1.9301x over previous
#include <cuda_runtime.h>
#include <cuda_bf16.h>
#include <cstdint>

typedef unsigned long long ull;

#define VV 32000
#define EE 32
#define HH 128
#define BB 2
#define TT 512
#define RR (BB*TT)                       // 1024
#define GK 384                           // K of split GEMM: [hi|hi|lo] x [hi|lo|hi]
#define OFF_HID (RR*VV)                  // 32768000
#define OFF_W   (OFF_HID + BB*HH)        // 32768256

// ---------------- scratch (static device globals; no allocation) ----------------
__device__ float g_xp [RR*HH];
__device__ float g_rnn[RR*HH];
__device__ float g_q  [RR*HH];
__device__ float g_k  [RR*HH];
__device__ float g_ctx[RR*HH];
__device__ int   g_x64;
__device__ __align__(16) __nv_bfloat16 g_prjA[RR*GK];
__device__ __align__(16) __nv_bfloat16 g_wfcB[(size_t)VV*GK];

// ---------------- helpers ----------------
__device__ __forceinline__ void fma2(ull &d, ull a, ull b) {
    asm("fma.rn.f32x2 %0, %1, %2, %0;" : "+l"(d) : "l"(a), "l"(b));
}
__device__ __forceinline__ float ull_lo(ull u){ return __uint_as_float((unsigned)(u & 0xffffffffull)); }
__device__ __forceinline__ float ull_hi(ull u){ return __uint_as_float((unsigned)(u >> 32)); }

__device__ __forceinline__ float tanh_fast(float x) {
    float e = __expf(2.0f * x);
    return 1.0f - __fdividef(2.0f, e + 1.0f);
}
__device__ __forceinline__ float tanh_approx(float x) {
    float y;
    asm("tanh.approx.f32 %0, %1;" : "=f"(y) : "f"(x));
    return y;
}
__device__ __forceinline__ void bf16_split(float f, __nv_bfloat16 &hi, __nv_bfloat16 &lo) {
    hi = __float2bfloat16(f);
    lo = __float2bfloat16(f - __bfloat162float(hi));
}
__device__ __forceinline__ uint32_t smem_to_u32(const void* p) {
    uint32_t a;
    asm("{ .reg .u64 t; cvta.to.shared.u64 t, %1; cvt.u32.u64 %0, t; }" : "=r"(a) : "l"(p));
    return a;
}

// ---------------- K0: detect int64 vs int32 ids ----------------
__global__ void detect_kernel(const int* __restrict__ x32) {
    __shared__ int bad;
    if (threadIdx.x == 0) bad = 0;
    __syncthreads();
    for (int i = threadIdx.x; i < 512; i += blockDim.x)
        if (x32[2*i + 1] != 0) atomicExch(&bad, 1);
    __syncthreads();
    if (threadIdx.x == 0) g_x64 = bad ? 0 : 1;
}

// ---------------- K1: embedding + input projection ----------------
__global__ void embed_kernel(const int* __restrict__ x32,
                             const float* __restrict__ et,
                             const float* __restrict__ W_ih,
                             const float* __restrict__ b_ih,
                             const float* __restrict__ b_hh) {
    __shared__ float e_sh[EE];
    __shared__ float Wsh[HH * 33];
    int r = blockIdx.x;
    int h = threadIdx.x;
    for (int j = h; j < HH * EE; j += HH) {
        int hh = j >> 5, ee = j & 31;
        Wsh[hh * 33 + ee] = W_ih[j];
    }
    int id = g_x64 ? x32[2 * r] : x32[r];
    if (h < EE) e_sh[h] = et[id * EE + h];
    __syncthreads();
    float acc = b_ih[h] + b_hh[h];
#pragma unroll
    for (int e = 0; e < EE; e++) acc += Wsh[h * 33 + e] * e_sh[e];
    g_xp[r * HH + h] = acc;
}

// ---------------- K2: sequential RNN scan ----------------
__global__ void rnn_kernel(const float* __restrict__ hidden,
                           const float* __restrict__ W_hh,
                           float* __restrict__ out_hid) {
    __shared__ __align__(16) float h_sh[2][HH];
    int b = blockIdx.x;
    int tid = threadIdx.x;
    int h = tid >> 2, part = tid & 3;

    ull w2[16];
    {
        const ulonglong2* wp = (const ulonglong2*)(W_hh + h * HH + part * 32);
#pragma unroll
        for (int i = 0; i < 8; i++) { ulonglong2 v = wp[i]; w2[2*i] = v.x; w2[2*i+1] = v.y; }
    }
    if (tid < HH) h_sh[0][tid] = hidden[b * HH + tid];
    __syncthreads();

    const float* xpb = g_xp + b * TT * HH;
    float* rnnb = g_rnn + b * TT * HH;

    float xnext = xpb[h];
    for (int t = 0; t < TT; t++) {
        float xcur = xnext;
        if (t + 1 < TT) xnext = xpb[(t + 1) * HH + h];
        int cur = t & 1;
        const ulonglong2* hp = (const ulonglong2*)(&h_sh[cur][part * 32]);
        ull a0 = 0ull, a1 = 0ull;
#pragma unroll
        for (int i = 0; i < 8; i++) {
            ulonglong2 hh2 = hp[i];
            fma2(a0, w2[2*i],   hh2.x);
            fma2(a1, w2[2*i+1], hh2.y);
        }
        float s = ull_lo(a0) + ull_hi(a0) + ull_lo(a1) + ull_hi(a1);
        s += __shfl_xor_sync(0xffffffffu, s, 1);
        s += __shfl_xor_sync(0xffffffffu, s, 2);
        if (part == 0) {
            float hn = tanh_fast(xcur + s);
            h_sh[cur ^ 1][h] = hn;
            rnnb[t * HH + h] = hn;
        }
        __syncthreads();
    }
    if (part == 0) out_hid[b * HH + h] = h_sh[0][h];
}

// ---------------- K3: q = rnn@W1^T, k = rnn@W2^T ----------------
__global__ __launch_bounds__(256, 2) void qk_kernel(const float* __restrict__ W1,
                                                    const float* __restrict__ W2) {
    extern __shared__ float qsm[];
    float* Wt  = qsm;              // [k=128][h=128] pitch 132
    float* rsh = qsm + 128 * 132;  // [r=32][k=128] pitch 132
    int wsel = blockIdx.x >> 5, tc = blockIdx.x & 31;
    const float* W = wsel ? W2 : W1;
    int tid = threadIdx.x;

#pragma unroll
    for (int it = 0; it < 16; it++) {
        int j = it * 256 + tid;
        int h = j >> 5, k4 = j & 31;
        float4 f = *(const float4*)&W[h * HH + k4 * 4];
        Wt[(k4 * 4 + 0) * 132 + h] = f.x;
        Wt[(k4 * 4 + 1) * 132 + h] = f.y;
        Wt[(k4 * 4 + 2) * 132 + h] = f.z;
        Wt[(k4 * 4 + 3) * 132 + h] = f.w;
    }
#pragma unroll
    for (int it = 0; it < 4; it++) {
        int j = it * 256 + tid;
        int r = j >> 5, k4 = j & 31;
        *(float4*)&rsh[r * 132 + k4 * 4] = *(const float4*)&g_rnn[(tc * 32 + r) * HH + k4 * 4];
    }
    __syncthreads();

    int h = tid & 127, rg = tid >> 7;
    float acc[16];
#pragma unroll
    for (int i = 0; i < 16; i++) acc[i] = 0.f;

    for (int k = 0; k < 128; k += 4) {
        float w0 = Wt[(k + 0) * 132 + h];
        float w1 = Wt[(k + 1) * 132 + h];
        float w2v = Wt[(k + 2) * 132 + h];
        float w3 = Wt[(k + 3) * 132 + h];
#pragma unroll
        for (int rr = 0; rr < 16; rr++) {
            float4 rv = *(const float4*)&rsh[(rg * 16 + rr) * 132 + k];
            acc[rr] += w0 * rv.x + w1 * rv.y + w2v * rv.z + w3 * rv.w;
        }
    }
    float* dst = wsel ? g_k : g_q;
#pragma unroll
    for (int rr = 0; rr < 16; rr++)
        dst[(tc * 32 + rg * 16 + rr) * HH + h] = acc[rr];
}

// ---------------- K4: additive attention ----------------
__global__ void attn_kernel(const float* __restrict__ v, float* __restrict__ wout) {
    __shared__ float q_sh[HH], v_sh[HH];
    __shared__ float ksh[64 * 132];
    __shared__ float sc[TT];
    __shared__ float red[8];
    __shared__ float redval;
    __shared__ float ctxp[HH];

    int bx = blockIdx.x;
    int b = bx >> 9, t = bx & 511;
    int tid = threadIdx.x;
    int r = b * TT + t;
    int n = t + 1;

    if (tid < HH) { q_sh[tid] = g_q[r * HH + tid]; v_sh[tid] = v[tid]; }
    __syncthreads();

    int sl = tid >> 2, qq = tid & 3;
    for (int s0 = 0; s0 < n; s0 += 64) {
        int cnt = min(64, n - s0);
        __syncthreads();
        for (int j = tid; j < cnt * HH; j += 256) {
            int ss = j >> 7, hh = j & 127;
            ksh[ss * 132 + hh] = g_k[(b * TT + s0 + ss) * HH + hh];
        }
        __syncthreads();
        float acc = 0.f;
        if (sl < cnt) {
            const float* kr = &ksh[sl * 132];
#pragma unroll 8
            for (int i = 0; i < 32; i++) {
                int hh = qq + 4 * i;
                acc += v_sh[hh] * tanh_approx(q_sh[hh] + kr[hh]);
            }
        }
        acc += __shfl_xor_sync(0xffffffffu, acc, 1);
        acc += __shfl_xor_sync(0xffffffffu, acc, 2);
        if (qq == 0 && sl < cnt) sc[s0 + sl] = acc;
    }
    __syncthreads();

    float m = -1e30f;
    for (int s = tid; s < n; s += 256) m = fmaxf(m, sc[s]);
#pragma unroll
    for (int o = 16; o; o >>= 1) m = fmaxf(m, __shfl_xor_sync(0xffffffffu, m, o));
    if ((tid & 31) == 0) red[tid >> 5] = m;
    __syncthreads();
    if (tid == 0) {
        float mm = red[0];
#pragma unroll
        for (int i = 1; i < 8; i++) mm = fmaxf(mm, red[i]);
        redval = mm;
    }
    __syncthreads();
    m = redval;

    float ssum = 0.f;
    for (int s = tid; s < n; s += 256) {
        float e = __expf(sc[s] - m);
        sc[s] = e;
        ssum += e;
    }
#pragma unroll
    for (int o = 16; o; o >>= 1) ssum += __shfl_xor_sync(0xffffffffu, ssum, o);
    __syncthreads();
    if ((tid & 31) == 0) red[tid >> 5] = ssum;
    __syncthreads();
    if (tid == 0) {
        float s2 = 0.f;
#pragma unroll
        for (int i = 0; i < 8; i++) s2 += red[i];
        redval = s2;
    }
    __syncthreads();
    float inv = __fdividef(1.0f, redval);

    for (int s = tid; s < TT; s += 256) {
        float w = (s < n) ? sc[s] * inv : 0.f;
        if (s < n) sc[s] = w;
        wout[(size_t)r * TT + s] = w;
    }
    __syncthreads();

    int h = tid & 127, g = tid >> 7;
    float acc = 0.f;
    for (int s = g; s < n; s += 2)
        acc += sc[s] * g_rnn[(b * TT + s) * HH + h];
    if (g == 1) ctxp[h] = acc;
    __syncthreads();
    if (g == 0) g_ctx[r * HH + h] = acc + ctxp[h];
}

// ---------------- K5: out = relu([rnn|ctx] @ Wp^T + bp) -> A' = [hi|hi|lo] bf16 ----------------
__global__ void proj_kernel(const float* __restrict__ Wp, const float* __restrict__ bp) {
    __shared__ float comb[16 * 256];
    __shared__ float Wsh[HH * 33];
    int bx = blockIdx.x;
    int b = bx >> 5, tc = bx & 31;
    int tid = threadIdx.x;
    int h = tid & 127, g = tid >> 7;
    int rbase = b * TT + tc * 16;

    for (int j = tid; j < 16 * HH; j += 256) {
        int tt = j >> 7, k = j & 127;
        comb[tt * 256 + k]        = g_rnn[(rbase + tt) * HH + k];
        comb[tt * 256 + 128 + k]  = g_ctx[(rbase + tt) * HH + k];
    }
    float acc[8];
#pragma unroll
    for (int i = 0; i < 8; i++) acc[i] = 0.f;

    for (int kc = 0; kc < 256; kc += 32) {
        __syncthreads();
        for (int j = tid; j < HH * 32; j += 256) {
            int hh = j >> 5, kk = j & 31;
            Wsh[hh * 33 + kk] = Wp[hh * 256 + kc + kk];
        }
        __syncthreads();
#pragma unroll
        for (int kk = 0; kk < 32; kk++) {
            float w = Wsh[h * 33 + kk];
#pragma unroll
            for (int tt = 0; tt < 8; tt++)
                acc[tt] += w * comb[(g * 8 + tt) * 256 + kc + kk];
        }
    }
    float bb = bp[h];
#pragma unroll
    for (int tt = 0; tt < 8; tt++) {
        float o = fmaxf(acc[tt] + bb, 0.f);
        size_t row = rbase + g * 8 + tt;
        __nv_bfloat16 hi, lo;
        bf16_split(o, hi, lo);
        g_prjA[row * GK + h]       = hi;
        g_prjA[row * GK + 128 + h] = hi;
        g_prjA[row * GK + 256 + h] = lo;
    }
}

// ---------------- K5b: Wfc -> B' = [hi|lo|hi] bf16 ----------------
__global__ void wfc_prep_kernel(const float* __restrict__ Wfc) {
    int j = blockIdx.x * 256 + threadIdx.x;   // over VV*HH/4 float4s
    float4 f = *(const float4*)&Wfc[(size_t)j * 4];
    int row = j >> 5;
    int col = (j & 31) * 4;
    __nv_bfloat16 h[4], l[4];
    bf16_split(f.x, h[0], l[0]);
    bf16_split(f.y, h[1], l[1]);
    bf16_split(f.z, h[2], l[2]);
    bf16_split(f.w, h[3], l[3]);
    size_t base = (size_t)row * GK;
    __nv_bfloat162* p0 = (__nv_bfloat162*)&g_wfcB[base + col];
    __nv_bfloat162* p1 = (__nv_bfloat162*)&g_wfcB[base + 128 + col];
    __nv_bfloat162* p2 = (__nv_bfloat162*)&g_wfcB[base + 256 + col];
    p0[0] = __nv_bfloat162(h[0], h[1]); p0[1] = __nv_bfloat162(h[2], h[3]);
    p1[0] = __nv_bfloat162(l[0], l[1]); p1[1] = __nv_bfloat162(l[2], l[3]);
    p2[0] = __nv_bfloat162(h[0], h[1]); p2[1] = __nv_bfloat162(h[2], h[3]);
}

// ---------------- K6: logits = A'(1024xGK) @ B'(32000xGK)^T + bfc, via mma.sync bf16 ----------------
// CTA: 128 tokens x 128 vocab. 8 warps (2m x 4n), warp tile 64x32, m16n8k16.
// K chunked by 64, cp.async double-buffered smem, XOR-swizzled 16B chunks for ldmatrix.
#define NCHUNK (GK/64)   // 6
__global__ __launch_bounds__(256, 2) void logits_mma_kernel(const float* __restrict__ bfc,
                                                            float* __restrict__ out) {
    extern __shared__ char sm[];
    uint32_t smb = smem_to_u32(sm);
    float* biassh = (float*)(sm + 65536);
    int vbase = blockIdx.x * 128;
    int rbase = blockIdx.y * 128;
    int tid = threadIdx.x;
    int wid = tid >> 5, lane = tid & 31;

    if (tid < 128) biassh[tid] = bfc[vbase + tid];

    // stage K-chunk c into smem buffer s (A tile 16KB + B tile 16KB), via cp.async
    auto stage = [&](int s, int c) {
        const char* srcA = (const char*)(g_prjA + (size_t)rbase * GK + c * 64);
        const char* srcB = (const char*)(g_wfcB + (size_t)vbase * GK + c * 64);
#pragma unroll
        for (int it = 0; it < 4; it++) {
            int j = it * 256 + tid;
            int r = j >> 3, cc = j & 7;
            uint32_t swoff = (uint32_t)(r * 128 + ((cc ^ (r & 7)) << 4));
            uint32_t dA = smb + s * 32768 + swoff;
            uint32_t dB = smb + s * 32768 + 16384 + swoff;
            const char* sA = srcA + (size_t)r * (GK * 2) + cc * 16;
            const char* sB = srcB + (size_t)r * (GK * 2) + cc * 16;
            asm volatile("cp.async.cg.shared.global [%0], [%1], 16;" :: "r"(dA), "l"(sA));
            asm volatile("cp.async.cg.shared.global [%0], [%1], 16;" :: "r"(dB), "l"(sB));
        }
        asm volatile("cp.async.commit_group;");
    };

    int warp_m = wid >> 2, warp_n = wid & 3;

    float acc[4][4][4];
#pragma unroll
    for (int i = 0; i < 4; i++)
#pragma unroll
        for (int j = 0; j < 4; j++)
#pragma unroll
            for (int p = 0; p < 4; p++) acc[i][j][p] = 0.f;

    stage(0, 0);
    stage(1, 1);

    int arowc = (lane & 7) + ((lane >> 3) & 1) * 8;   // row-within-16 for ldmatrix x4
    int chnksel = lane >> 4;                          // k-half selector

    for (int c = 0; c < NCHUNK; c++) {
        if (c == NCHUNK - 1) { asm volatile("cp.async.wait_group 0;" ::: "memory"); }
        else                 { asm volatile("cp.async.wait_group 1;" ::: "memory"); }
        __syncthreads();
        uint32_t Ab = smb + (c & 1) * 32768;
        uint32_t Bb = Ab + 16384;
#pragma unroll
        for (int kk = 0; kk < 4; kk++) {
            uint32_t a[4][4], bfr[2][4];
            int chnk = kk * 2 + chnksel;
#pragma unroll
            for (int mt = 0; mt < 4; mt++) {
                int row = warp_m * 64 + mt * 16 + arowc;
                uint32_t addr = Ab + row * 128 + ((chnk ^ (row & 7)) << 4);
                asm volatile("ldmatrix.sync.aligned.m8n8.x4.shared.b16 {%0,%1,%2,%3}, [%4];"
                    : "=r"(a[mt][0]), "=r"(a[mt][1]), "=r"(a[mt][2]), "=r"(a[mt][3]) : "r"(addr));
            }
#pragma unroll
            for (int bp = 0; bp < 2; bp++) {
                int row = warp_n * 32 + bp * 16 + arowc;
                uint32_t addr = Bb + row * 128 + ((chnk ^ (row & 7)) << 4);
                asm volatile("ldmatrix.sync.aligned.m8n8.x4.shared.b16 {%0,%1,%2,%3}, [%4];"
                    : "=r"(bfr[bp][0]), "=r"(bfr[bp][1]), "=r"(bfr[bp][2]), "=r"(bfr[bp][3]) : "r"(addr));
            }
#pragma unroll
            for (int mt = 0; mt < 4; mt++)
#pragma unroll
                for (int nt = 0; nt < 4; nt++) {
                    uint32_t b0 = bfr[nt >> 1][(nt & 1) ? 1 : 0];
                    uint32_t b1 = bfr[nt >> 1][(nt & 1) ? 3 : 2];
                    asm volatile("mma.sync.aligned.m16n8k16.row.col.f32.bf16.bf16.f32 "
                        "{%0,%1,%2,%3}, {%4,%5,%6,%7}, {%8,%9}, {%0,%1,%2,%3};"
                        : "+f"(acc[mt][nt][0]), "+f"(acc[mt][nt][1]),
                          "+f"(acc[mt][nt][2]), "+f"(acc[mt][nt][3])
                        : "r"(a[mt][0]), "r"(a[mt][1]), "r"(a[mt][2]), "r"(a[mt][3]),
                          "r"(b0), "r"(b1));
                }
        }
        __syncthreads();
        if (c + 2 < NCHUNK) stage(c & 1, c + 2);
    }

    // epilogue: c-frag rows = lane/4 (+8), cols = 2*(lane%4)+{0,1}
    int rquad = lane >> 2, cpair = (lane & 3) * 2;
#pragma unroll
    for (int mt = 0; mt < 4; mt++) {
#pragma unroll
        for (int nt = 0; nt < 4; nt++) {
            int col = warp_n * 32 + nt * 8 + cpair;
            float bx = biassh[col], by = biassh[col + 1];
            size_t row0 = (size_t)rbase + warp_m * 64 + mt * 16 + rquad;
            float2 v0 = { acc[mt][nt][0] + bx, acc[mt][nt][1] + by };
            float2 v1 = { acc[mt][nt][2] + bx, acc[mt][nt][3] + by };
            *(float2*)&out[row0 * VV + vbase + col]       = v0;
            *(float2*)&out[(row0 + 8) * VV + vbase + col] = v1;
        }
    }
}

// ---------------- launch ----------------
extern "C" void kernel_launch(void* const* d_in, const int* in_sizes, int n_in,
                              void* d_out, int out_size) {
    const int*   x32    = (const int*)  d_in[0];
    const float* hidden = (const float*)d_in[1];
    const float* et     = (const float*)d_in[2];
    const float* W_ih   = (const float*)d_in[3];
    const float* W_hh   = (const float*)d_in[4];
    const float* b_ih   = (const float*)d_in[5];
    const float* b_hh   = (const float*)d_in[6];
    const float* W1     = (const float*)d_in[7];
    const float* W2     = (const float*)d_in[8];
    const float* v      = (const float*)d_in[9];
    const float* Wp     = (const float*)d_in[10];
    const float* bp     = (const float*)d_in[11];
    const float* Wfc    = (const float*)d_in[12];
    const float* bfc    = (const float*)d_in[13];
    float* out = (float*)d_out;

    cudaFuncSetAttribute(qk_kernel,         cudaFuncAttributeMaxDynamicSharedMemorySize, 84480);
    cudaFuncSetAttribute(logits_mma_kernel, cudaFuncAttributeMaxDynamicSharedMemorySize, 66048);

    detect_kernel<<<1, 256>>>(x32);
    embed_kernel<<<RR, HH>>>(x32, et, W_ih, b_ih, b_hh);
    wfc_prep_kernel<<<VV * HH / 1024, 256>>>(Wfc);
    rnn_kernel<<<BB, 512>>>(hidden, W_hh, out + OFF_HID);
    qk_kernel<<<64, 256, 84480>>>(W1, W2);
    attn_kernel<<<RR, 256>>>(v, out + OFF_W);
    proj_kernel<<<64, 256>>>(Wp, bp);
    logits_mma_kernel<<<dim3(VV / 128, RR / 128), 256, 66048>>>(bfc, out);
}

// round 9
// speedup vs baseline: 3.9031x; 2.0223x over previous
#include <cuda_runtime.h>
#include <cuda_bf16.h>
#include <cstdint>

typedef unsigned long long ull;

#define VV 32000
#define EE 32
#define HH 128
#define BB 2
#define TT 512
#define RR (BB*TT)                       // 1024
#define GK 384                           // K of split GEMM: [hi|hi|lo] x [hi|lo|hi]
#define OFF_HID (RR*VV)                  // 32768000
#define OFF_W   (OFF_HID + BB*HH)        // 32768256

// ---------------- scratch (static device globals; no allocation) ----------------
__device__ float g_xp [RR*HH];
__device__ float g_rnn[RR*HH];
__device__ float g_q  [RR*HH];
__device__ float g_k  [RR*HH];
__device__ float g_ctx[RR*HH];
__device__ int   g_x64;
__device__ __align__(16) __nv_bfloat16 g_prjA[RR*GK];
__device__ __align__(16) __nv_bfloat16 g_wfcB[(size_t)VV*GK];

// ---------------- helpers ----------------
__device__ __forceinline__ void fma2(ull &d, ull a, ull b) {
    asm("fma.rn.f32x2 %0, %1, %2, %0;" : "+l"(d) : "l"(a), "l"(b));
}
__device__ __forceinline__ void add2(ull &d, ull a) {
    asm("add.rn.f32x2 %0, %0, %1;" : "+l"(d) : "l"(a));
}
__device__ __forceinline__ float ull_lo(ull u){ return __uint_as_float((unsigned)(u & 0xffffffffull)); }
__device__ __forceinline__ float ull_hi(ull u){ return __uint_as_float((unsigned)(u >> 32)); }

__device__ __forceinline__ float tanh_fast(float x) {
    float e = __expf(2.0f * x);
    return 1.0f - __fdividef(2.0f, e + 1.0f);
}
__device__ __forceinline__ float tanh_approx(float x) {
    float y;
    asm("tanh.approx.f32 %0, %1;" : "=f"(y) : "f"(x));
    return y;
}
__device__ __forceinline__ void bf16_split(float f, __nv_bfloat16 &hi, __nv_bfloat16 &lo) {
    hi = __float2bfloat16(f);
    lo = __float2bfloat16(f - __bfloat162float(hi));
}
__device__ __forceinline__ uint32_t smem_to_u32(const void* p) {
    uint32_t a;
    asm("{ .reg .u64 t; cvta.to.shared.u64 t, %1; cvt.u32.u64 %0, t; }" : "=r"(a) : "l"(p));
    return a;
}

// ---------------- K0: detect int64 vs int32 ids ----------------
__global__ void detect_kernel(const int* __restrict__ x32) {
    __shared__ int bad;
    if (threadIdx.x == 0) bad = 0;
    __syncthreads();
    for (int i = threadIdx.x; i < 512; i += blockDim.x)
        if (x32[2*i + 1] != 0) atomicExch(&bad, 1);
    __syncthreads();
    if (threadIdx.x == 0) g_x64 = bad ? 0 : 1;
}

// ---------------- K1: embedding + input projection ----------------
__global__ void embed_kernel(const int* __restrict__ x32,
                             const float* __restrict__ et,
                             const float* __restrict__ W_ih,
                             const float* __restrict__ b_ih,
                             const float* __restrict__ b_hh) {
    __shared__ float e_sh[EE];
    __shared__ float Wsh[HH * 33];
    int r = blockIdx.x;
    int h = threadIdx.x;
    for (int j = h; j < HH * EE; j += HH) {
        int hh = j >> 5, ee = j & 31;
        Wsh[hh * 33 + ee] = W_ih[j];
    }
    int id = g_x64 ? x32[2 * r] : x32[r];
    if (h < EE) e_sh[h] = et[id * EE + h];
    __syncthreads();
    float acc = b_ih[h] + b_hh[h];
#pragma unroll
    for (int e = 0; e < EE; e++) acc += Wsh[h * 33 + e] * e_sh[e];
    g_xp[r * HH + h] = acc;
}

// ---------------- K2: sequential RNN scan (256 thr, 2-way K split, deep xp prefetch) ----------------
__global__ void __launch_bounds__(256, 1) rnn_kernel(const float* __restrict__ hidden,
                                                     const float* __restrict__ W_hh,
                                                     float* __restrict__ out_hid) {
    __shared__ __align__(16) float h_sh[2][HH];
    int b = blockIdx.x;
    int tid = threadIdx.x;
    int h = tid >> 1, part = tid & 1;

    // thread (h, part) holds W_hh[h][part*64 .. +64) as 32 packed f32x2 regs
    ull w2[32];
    {
        const ulonglong2* wp = (const ulonglong2*)(W_hh + h * HH + part * 64);
#pragma unroll
        for (int i = 0; i < 16; i++) { ulonglong2 v = wp[i]; w2[2*i] = v.x; w2[2*i+1] = v.y; }
    }
    if (tid < HH) h_sh[0][tid] = hidden[b * HH + tid];
    __syncthreads();

    const float* xpb = g_xp + b * TT * HH;
    float* rnnb = g_rnn + b * TT * HH;

    // xp register pipeline, depth 2 (only part==0 consumes xp)
    float x0 = 0.f, x1 = 0.f;
    if (part == 0) { x0 = xpb[h]; x1 = xpb[HH + h]; }

#pragma unroll 2
    for (int t = 0; t < TT; t++) {
        int cur = t & 1;
        float xnew = 0.f;
        if (part == 0 && t + 2 < TT) xnew = xpb[(t + 2) * HH + h];   // prefetch t+2

        const ulonglong2* hp = (const ulonglong2*)&h_sh[cur][part * 64];
        ull a0 = 0ull, a1 = 0ull, a2 = 0ull, a3 = 0ull;
#pragma unroll
        for (int i = 0; i < 8; i++) {
            ulonglong2 u = hp[2*i];
            ulonglong2 v = hp[2*i+1];
            fma2(a0, w2[4*i+0], u.x);
            fma2(a1, w2[4*i+1], u.y);
            fma2(a2, w2[4*i+2], v.x);
            fma2(a3, w2[4*i+3], v.y);
        }
        add2(a0, a1);
        add2(a2, a3);
        add2(a0, a2);
        float s = ull_lo(a0) + ull_hi(a0);
        s += __shfl_xor_sync(0xffffffffu, s, 1);   // combine part 0/1 (adjacent lanes)
        if (part == 0) {
            float hn = tanh_fast(x0 + s);
            h_sh[cur ^ 1][h] = hn;
            rnnb[t * HH + h] = hn;
        }
        x0 = x1; x1 = xnew;
        __syncthreads();
    }
    if (part == 0) out_hid[b * HH + h] = h_sh[0][h];
}

// ---------------- K3: q = rnn@W1^T, k = rnn@W2^T ----------------
__global__ __launch_bounds__(256, 2) void qk_kernel(const float* __restrict__ W1,
                                                    const float* __restrict__ W2) {
    extern __shared__ float qsm[];
    float* Wt  = qsm;              // [k=128][h=128] pitch 132
    float* rsh = qsm + 128 * 132;  // [r=32][k=128] pitch 132
    int wsel = blockIdx.x >> 5, tc = blockIdx.x & 31;
    const float* W = wsel ? W2 : W1;
    int tid = threadIdx.x;

#pragma unroll
    for (int it = 0; it < 16; it++) {
        int j = it * 256 + tid;
        int h = j >> 5, k4 = j & 31;
        float4 f = *(const float4*)&W[h * HH + k4 * 4];
        Wt[(k4 * 4 + 0) * 132 + h] = f.x;
        Wt[(k4 * 4 + 1) * 132 + h] = f.y;
        Wt[(k4 * 4 + 2) * 132 + h] = f.z;
        Wt[(k4 * 4 + 3) * 132 + h] = f.w;
    }
#pragma unroll
    for (int it = 0; it < 4; it++) {
        int j = it * 256 + tid;
        int r = j >> 5, k4 = j & 31;
        *(float4*)&rsh[r * 132 + k4 * 4] = *(const float4*)&g_rnn[(tc * 32 + r) * HH + k4 * 4];
    }
    __syncthreads();

    int h = tid & 127, rg = tid >> 7;
    float acc[16];
#pragma unroll
    for (int i = 0; i < 16; i++) acc[i] = 0.f;

    for (int k = 0; k < 128; k += 4) {
        float w0 = Wt[(k + 0) * 132 + h];
        float w1 = Wt[(k + 1) * 132 + h];
        float w2v = Wt[(k + 2) * 132 + h];
        float w3 = Wt[(k + 3) * 132 + h];
#pragma unroll
        for (int rr = 0; rr < 16; rr++) {
            float4 rv = *(const float4*)&rsh[(rg * 16 + rr) * 132 + k];
            acc[rr] += w0 * rv.x + w1 * rv.y + w2v * rv.z + w3 * rv.w;
        }
    }
    float* dst = wsel ? g_k : g_q;
#pragma unroll
    for (int rr = 0; rr < 16; rr++)
        dst[(tc * 32 + rg * 16 + rr) * HH + h] = acc[rr];
}

// ---------------- K4: additive attention ----------------
__global__ void attn_kernel(const float* __restrict__ v, float* __restrict__ wout) {
    __shared__ float q_sh[HH], v_sh[HH];
    __shared__ float ksh[64 * 132];
    __shared__ float sc[TT];
    __shared__ float red[8];
    __shared__ float redval;
    __shared__ float ctxp[HH];

    int bx = blockIdx.x;
    int b = bx >> 9, t = bx & 511;
    int tid = threadIdx.x;
    int r = b * TT + t;
    int n = t + 1;

    if (tid < HH) { q_sh[tid] = g_q[r * HH + tid]; v_sh[tid] = v[tid]; }
    __syncthreads();

    int sl = tid >> 2, qq = tid & 3;
    for (int s0 = 0; s0 < n; s0 += 64) {
        int cnt = min(64, n - s0);
        __syncthreads();
        for (int j = tid; j < cnt * HH; j += 256) {
            int ss = j >> 7, hh = j & 127;
            ksh[ss * 132 + hh] = g_k[(b * TT + s0 + ss) * HH + hh];
        }
        __syncthreads();
        float acc = 0.f;
        if (sl < cnt) {
            const float* kr = &ksh[sl * 132];
#pragma unroll 8
            for (int i = 0; i < 32; i++) {
                int hh = qq + 4 * i;
                acc += v_sh[hh] * tanh_approx(q_sh[hh] + kr[hh]);
            }
        }
        acc += __shfl_xor_sync(0xffffffffu, acc, 1);
        acc += __shfl_xor_sync(0xffffffffu, acc, 2);
        if (qq == 0 && sl < cnt) sc[s0 + sl] = acc;
    }
    __syncthreads();

    float m = -1e30f;
    for (int s = tid; s < n; s += 256) m = fmaxf(m, sc[s]);
#pragma unroll
    for (int o = 16; o; o >>= 1) m = fmaxf(m, __shfl_xor_sync(0xffffffffu, m, o));
    if ((tid & 31) == 0) red[tid >> 5] = m;
    __syncthreads();
    if (tid == 0) {
        float mm = red[0];
#pragma unroll
        for (int i = 1; i < 8; i++) mm = fmaxf(mm, red[i]);
        redval = mm;
    }
    __syncthreads();
    m = redval;

    float ssum = 0.f;
    for (int s = tid; s < n; s += 256) {
        float e = __expf(sc[s] - m);
        sc[s] = e;
        ssum += e;
    }
#pragma unroll
    for (int o = 16; o; o >>= 1) ssum += __shfl_xor_sync(0xffffffffu, ssum, o);
    __syncthreads();
    if ((tid & 31) == 0) red[tid >> 5] = ssum;
    __syncthreads();
    if (tid == 0) {
        float s2 = 0.f;
#pragma unroll
        for (int i = 0; i < 8; i++) s2 += red[i];
        redval = s2;
    }
    __syncthreads();
    float inv = __fdividef(1.0f, redval);

    for (int s = tid; s < TT; s += 256) {
        float w = (s < n) ? sc[s] * inv : 0.f;
        if (s < n) sc[s] = w;
        wout[(size_t)r * TT + s] = w;
    }
    __syncthreads();

    int h = tid & 127, g = tid >> 7;
    float acc = 0.f;
    for (int s = g; s < n; s += 2)
        acc += sc[s] * g_rnn[(b * TT + s) * HH + h];
    if (g == 1) ctxp[h] = acc;
    __syncthreads();
    if (g == 0) g_ctx[r * HH + h] = acc + ctxp[h];
}

// ---------------- K5: out = relu([rnn|ctx] @ Wp^T + bp) -> A' = [hi|hi|lo] bf16 ----------------
__global__ void proj_kernel(const float* __restrict__ Wp, const float* __restrict__ bp) {
    __shared__ float comb[16 * 256];
    __shared__ float Wsh[HH * 33];
    int bx = blockIdx.x;
    int b = bx >> 5, tc = bx & 31;
    int tid = threadIdx.x;
    int h = tid & 127, g = tid >> 7;
    int rbase = b * TT + tc * 16;

    for (int j = tid; j < 16 * HH; j += 256) {
        int tt = j >> 7, k = j & 127;
        comb[tt * 256 + k]        = g_rnn[(rbase + tt) * HH + k];
        comb[tt * 256 + 128 + k]  = g_ctx[(rbase + tt) * HH + k];
    }
    float acc[8];
#pragma unroll
    for (int i = 0; i < 8; i++) acc[i] = 0.f;

    for (int kc = 0; kc < 256; kc += 32) {
        __syncthreads();
        for (int j = tid; j < HH * 32; j += 256) {
            int hh = j >> 5, kk = j & 31;
            Wsh[hh * 33 + kk] = Wp[hh * 256 + kc + kk];
        }
        __syncthreads();
#pragma unroll
        for (int kk = 0; kk < 32; kk++) {
            float w = Wsh[h * 33 + kk];
#pragma unroll
            for (int tt = 0; tt < 8; tt++)
                acc[tt] += w * comb[(g * 8 + tt) * 256 + kc + kk];
        }
    }
    float bb = bp[h];
#pragma unroll
    for (int tt = 0; tt < 8; tt++) {
        float o = fmaxf(acc[tt] + bb, 0.f);
        size_t row = rbase + g * 8 + tt;
        __nv_bfloat16 hi, lo;
        bf16_split(o, hi, lo);
        g_prjA[row * GK + h]       = hi;
        g_prjA[row * GK + 128 + h] = hi;
        g_prjA[row * GK + 256 + h] = lo;
    }
}

// ---------------- K5b: Wfc -> B' = [hi|lo|hi] bf16 ----------------
__global__ void wfc_prep_kernel(const float* __restrict__ Wfc) {
    int j = blockIdx.x * 256 + threadIdx.x;   // over VV*HH/4 float4s
    float4 f = *(const float4*)&Wfc[(size_t)j * 4];
    int row = j >> 5;
    int col = (j & 31) * 4;
    __nv_bfloat16 h[4], l[4];
    bf16_split(f.x, h[0], l[0]);
    bf16_split(f.y, h[1], l[1]);
    bf16_split(f.z, h[2], l[2]);
    bf16_split(f.w, h[3], l[3]);
    size_t base = (size_t)row * GK;
    __nv_bfloat162* p0 = (__nv_bfloat162*)&g_wfcB[base + col];
    __nv_bfloat162* p1 = (__nv_bfloat162*)&g_wfcB[base + 128 + col];
    __nv_bfloat162* p2 = (__nv_bfloat162*)&g_wfcB[base + 256 + col];
    p0[0] = __nv_bfloat162(h[0], h[1]); p0[1] = __nv_bfloat162(h[2], h[3]);
    p1[0] = __nv_bfloat162(l[0], l[1]); p1[1] = __nv_bfloat162(l[2], l[3]);
    p2[0] = __nv_bfloat162(h[0], h[1]); p2[1] = __nv_bfloat162(h[2], h[3]);
}

// ---------------- K6: logits = A'(1024xGK) @ B'(32000xGK)^T + bfc, via mma.sync bf16 ----------------
#define NCHUNK (GK/64)   // 6
__global__ __launch_bounds__(256, 2) void logits_mma_kernel(const float* __restrict__ bfc,
                                                            float* __restrict__ out) {
    extern __shared__ char sm[];
    uint32_t smb = smem_to_u32(sm);
    float* biassh = (float*)(sm + 65536);
    int vbase = blockIdx.x * 128;
    int rbase = blockIdx.y * 128;
    int tid = threadIdx.x;
    int wid = tid >> 5, lane = tid & 31;

    if (tid < 128) biassh[tid] = bfc[vbase + tid];

    auto stage = [&](int s, int c) {
        const char* srcA = (const char*)(g_prjA + (size_t)rbase * GK + c * 64);
        const char* srcB = (const char*)(g_wfcB + (size_t)vbase * GK + c * 64);
#pragma unroll
        for (int it = 0; it < 4; it++) {
            int j = it * 256 + tid;
            int r = j >> 3, cc = j & 7;
            uint32_t swoff = (uint32_t)(r * 128 + ((cc ^ (r & 7)) << 4));
            uint32_t dA = smb + s * 32768 + swoff;
            uint32_t dB = smb + s * 32768 + 16384 + swoff;
            const char* sA = srcA + (size_t)r * (GK * 2) + cc * 16;
            const char* sB = srcB + (size_t)r * (GK * 2) + cc * 16;
            asm volatile("cp.async.cg.shared.global [%0], [%1], 16;" :: "r"(dA), "l"(sA));
            asm volatile("cp.async.cg.shared.global [%0], [%1], 16;" :: "r"(dB), "l"(sB));
        }
        asm volatile("cp.async.commit_group;");
    };

    int warp_m = wid >> 2, warp_n = wid & 3;

    float acc[4][4][4];
#pragma unroll
    for (int i = 0; i < 4; i++)
#pragma unroll
        for (int j = 0; j < 4; j++)
#pragma unroll
            for (int p = 0; p < 4; p++) acc[i][j][p] = 0.f;

    stage(0, 0);
    stage(1, 1);

    int arowc = (lane & 7) + ((lane >> 3) & 1) * 8;
    int chnksel = lane >> 4;

    for (int c = 0; c < NCHUNK; c++) {
        if (c == NCHUNK - 1) { asm volatile("cp.async.wait_group 0;" ::: "memory"); }
        else                 { asm volatile("cp.async.wait_group 1;" ::: "memory"); }
        __syncthreads();
        uint32_t Ab = smb + (c & 1) * 32768;
        uint32_t Bb = Ab + 16384;
#pragma unroll
        for (int kk = 0; kk < 4; kk++) {
            uint32_t a[4][4], bfr[2][4];
            int chnk = kk * 2 + chnksel;
#pragma unroll
            for (int mt = 0; mt < 4; mt++) {
                int row = warp_m * 64 + mt * 16 + arowc;
                uint32_t addr = Ab + row * 128 + ((chnk ^ (row & 7)) << 4);
                asm volatile("ldmatrix.sync.aligned.m8n8.x4.shared.b16 {%0,%1,%2,%3}, [%4];"
                    : "=r"(a[mt][0]), "=r"(a[mt][1]), "=r"(a[mt][2]), "=r"(a[mt][3]) : "r"(addr));
            }
#pragma unroll
            for (int bp = 0; bp < 2; bp++) {
                int row = warp_n * 32 + bp * 16 + arowc;
                uint32_t addr = Bb + row * 128 + ((chnk ^ (row & 7)) << 4);
                asm volatile("ldmatrix.sync.aligned.m8n8.x4.shared.b16 {%0,%1,%2,%3}, [%4];"
                    : "=r"(bfr[bp][0]), "=r"(bfr[bp][1]), "=r"(bfr[bp][2]), "=r"(bfr[bp][3]) : "r"(addr));
            }
#pragma unroll
            for (int mt = 0; mt < 4; mt++)
#pragma unroll
                for (int nt = 0; nt < 4; nt++) {
                    uint32_t b0 = bfr[nt >> 1][(nt & 1) ? 1 : 0];
                    uint32_t b1 = bfr[nt >> 1][(nt & 1) ? 3 : 2];
                    asm volatile("mma.sync.aligned.m16n8k16.row.col.f32.bf16.bf16.f32 "
                        "{%0,%1,%2,%3}, {%4,%5,%6,%7}, {%8,%9}, {%0,%1,%2,%3};"
                        : "+f"(acc[mt][nt][0]), "+f"(acc[mt][nt][1]),
                          "+f"(acc[mt][nt][2]), "+f"(acc[mt][nt][3])
                        : "r"(a[mt][0]), "r"(a[mt][1]), "r"(a[mt][2]), "r"(a[mt][3]),
                          "r"(b0), "r"(b1));
                }
        }
        __syncthreads();
        if (c + 2 < NCHUNK) stage(c & 1, c + 2);
    }

    int rquad = lane >> 2, cpair = (lane & 3) * 2;
#pragma unroll
    for (int mt = 0; mt < 4; mt++) {
#pragma unroll
        for (int nt = 0; nt < 4; nt++) {
            int col = warp_n * 32 + nt * 8 + cpair;
            float bx = biassh[col], by = biassh[col + 1];
            size_t row0 = (size_t)rbase + warp_m * 64 + mt * 16 + rquad;
            float2 v0 = { acc[mt][nt][0] + bx, acc[mt][nt][1] + by };
            float2 v1 = { acc[mt][nt][2] + bx, acc[mt][nt][3] + by };
            *(float2*)&out[row0 * VV + vbase + col]       = v0;
            *(float2*)&out[(row0 + 8) * VV + vbase + col] = v1;
        }
    }
}

// ---------------- launch ----------------
extern "C" void kernel_launch(void* const* d_in, const int* in_sizes, int n_in,
                              void* d_out, int out_size) {
    const int*   x32    = (const int*)  d_in[0];
    const float* hidden = (const float*)d_in[1];
    const float* et     = (const float*)d_in[2];
    const float* W_ih   = (const float*)d_in[3];
    const float* W_hh   = (const float*)d_in[4];
    const float* b_ih   = (const float*)d_in[5];
    const float* b_hh   = (const float*)d_in[6];
    const float* W1     = (const float*)d_in[7];
    const float* W2     = (const float*)d_in[8];
    const float* v      = (const float*)d_in[9];
    const float* Wp     = (const float*)d_in[10];
    const float* bp     = (const float*)d_in[11];
    const float* Wfc    = (const float*)d_in[12];
    const float* bfc    = (const float*)d_in[13];
    float* out = (float*)d_out;

    cudaFuncSetAttribute(qk_kernel,         cudaFuncAttributeMaxDynamicSharedMemorySize, 84480);
    cudaFuncSetAttribute(logits_mma_kernel, cudaFuncAttributeMaxDynamicSharedMemorySize, 66048);

    detect_kernel<<<1, 256>>>(x32);
    embed_kernel<<<RR, HH>>>(x32, et, W_ih, b_ih, b_hh);
    wfc_prep_kernel<<<VV * HH / 1024, 256>>>(Wfc);
    rnn_kernel<<<BB, 256>>>(hidden, W_hh, out + OFF_HID);
    qk_kernel<<<64, 256, 84480>>>(W1, W2);
    attn_kernel<<<RR, 256>>>(v, out + OFF_W);
    proj_kernel<<<64, 256>>>(Wp, bp);
    logits_mma_kernel<<<dim3(VV / 128, RR / 128), 256, 66048>>>(bfc, out);
}